// round 1
// baseline (speedup 1.0000x reference)
#include <cuda_runtime.h>
#include <math.h>

// LanczosUpsampling: (4,2,256,256) f32 -> (4,2,2048,2048), exact 8x separable lanczos(a=4).
//
// Reduction: with scale exactly 8, the 9-tap lanczos at upsampled resolution touches
// at most 2 source columns (rows) per output pixel, and only 8 LUT phases exist.
// => out[i,j] = cwTl*img[rT,cL] + cwTr*img[rT,cR] + cwBl*img[rB,cL] + cwBr*img[rB,cR]
// with per-(i%8, j%8) weights. Reflect padding (distance<=4 < block 8) is exactly an
// index clamp on the source grid.

namespace {
constexpr int HS = 256;
constexpr int WS = 256;
constexpr int HO = 2048;
constexpr int WO = 2048;
constexpr int NIMG = 8;  // B*C
}

// Combined 2x2 weights per (row-phase, col-phase): {Tl, Tr, Bl, Br}
__device__ float4 g_cw[8][8];

__global__ void lz_init_kernel() {
    __shared__ double s_l[8], s_r[8];
    const int t = threadIdx.x;
    if (t < 8) {
        // delta = 1e-8 + f/8 (LUT index 128*f of the reference table)
        const double delta = 1e-8 + t * 0.125;
        // taps p < s land in the LEFT source column, p >= s in the RIGHT one
        const int s = (t <= 3) ? (4 - t) : (12 - t);
        double wl = 0.0, wr = 0.0;
        #pragma unroll
        for (int p = 0; p < 9; ++p) {
            const double x = delta + (double)(p - 4);
            const double a = x * 3.14159265358979323846;
            const double b = a * 0.25;  // a = 4
            const double w = (sin(a) / a) * (sin(b) / b);
            if (p < s) wl += w; else wr += w;
        }
        s_l[t] = wl;
        s_r[t] = wr;
    }
    __syncthreads();
    if (t < 64) {
        const int fy = t >> 3;
        const int fx = t & 7;
        g_cw[fy][fx] = make_float4((float)(s_l[fy] * s_l[fx]),
                                   (float)(s_l[fy] * s_r[fx]),
                                   (float)(s_r[fy] * s_l[fx]),
                                   (float)(s_r[fy] * s_r[fx]));
    }
}

__global__ __launch_bounds__(256)
void lz_main_kernel(const float* __restrict__ img, float* __restrict__ out) {
    // One thread = 4 consecutive output pixels (one float4), perfectly coalesced.
    const unsigned gid = blockIdx.x * 256u + threadIdx.x;
    const int rowid = gid >> 9;           // global output row (bc*HO + i); uniform per warp
    const int j4    = gid & 511;          // float4 slot within the row
    const int i     = rowid & (HO - 1);
    const int bc    = rowid >> 11;
    const int fy    = i & 7;
    const int rb    = i >> 3;

    int rT = (fy <= 3) ? rb - 1 : rb;
    const int rB = min(rT + 1, HS - 1);
    rT = max(rT, 0);

    const float* __restrict__ srcT = img + ((size_t)bc * HS + (size_t)rT) * WS;
    const float* __restrict__ srcB = img + ((size_t)bc * HS + (size_t)rB) * WS;

    const int half = j4 & 1;              // 0 -> phases 0..3, 1 -> phases 4..7
    const int cb   = j4 >> 1;             // source column block
    int cL, cR;
    if (half == 0) { cL = max(cb - 1, 0); cR = cb; }
    else           { cL = cb;             cR = min(cb + 1, WS - 1); }

    const float tL = __ldg(srcT + cL);
    const float tR = __ldg(srcT + cR);
    const float bL = __ldg(srcB + cL);
    const float bR = __ldg(srcB + cR);

    const int f0 = half << 2;
    const float4 w0 = g_cw[fy][f0 + 0];
    const float4 w1 = g_cw[fy][f0 + 1];
    const float4 w2 = g_cw[fy][f0 + 2];
    const float4 w3 = g_cw[fy][f0 + 3];

    float4 o;
    o.x = w0.x * tL + w0.y * tR + w0.z * bL + w0.w * bR;
    o.y = w1.x * tL + w1.y * tR + w1.z * bL + w1.w * bR;
    o.z = w2.x * tL + w2.y * tR + w2.z * bL + w2.w * bR;
    o.w = w3.x * tL + w3.y * tR + w3.z * bL + w3.w * bR;

    reinterpret_cast<float4*>(out)[gid] = o;
}

extern "C" void kernel_launch(void* const* d_in, const int* in_sizes, int n_in,
                              void* d_out, int out_size) {
    (void)in_sizes; (void)n_in; (void)out_size;
    const float* img = (const float*)d_in[0];
    float* out = (float*)d_out;

    lz_init_kernel<<<1, 64>>>();

    const unsigned total_vec4 = (unsigned)NIMG * HO * WO / 4;  // 8,388,608
    lz_main_kernel<<<total_vec4 / 256, 256>>>(img, out);
}

// round 6
// speedup vs baseline: 2.3312x; 2.3312x over previous
#include <cuda_runtime.h>
#include <math.h>

// LanczosUpsampling: (4,2,256,256) f32 -> (4,2,2048,2048), exact 8x separable lanczos(a=4).
//
// With scale exactly 8 there are only 8 fractional phases, and each phase's 9 taps
// span at most 2 source samples per axis. Separable form:
//   out[8rb+fy, 8cb+fx] = wy{l,r}[fy] (x) wx{l,r}[fx] applied to a 2x2 source patch,
// where fy<=3 uses rows (rb-1, rb), fy>=4 uses (rb, rb+1) (same for columns),
// and reflect padding reduces exactly to index clamping.
//
// One thread produces a 4-wide x 8-tall output patch (32 px): 6 scalar source loads,
// horizontal pass per source row, then 8 vertical combines + 8 coalesced STG.128.
// Weights (128 B of constants) are computed on the host and passed by value in the
// kernel parameter block (constant bank) — no init kernel, no memcpy.

namespace {
constexpr int HS = 256;
constexpr int WS = 256;
constexpr int HO = 2048;
constexpr int NIMG = 8;  // B*C
constexpr int RBLK = HO / 8;  // 256 source row blocks per image
}

struct LzW {
    float wxl[8], wxr[8];  // horizontal left/right aggregated tap sums per phase
    float wyl[8], wyr[8];  // vertical
};

__global__ __launch_bounds__(256)
void lz_main_kernel(const float* __restrict__ img, float* __restrict__ out, LzW W) {
    const unsigned tid = blockIdx.x * 256u + threadIdx.x;
    const int j4   = tid & 511;           // float4 slot within an output row
    const int rb   = (tid >> 9) & 255;    // source row block (8 output rows); 256 per image
    const int bc   = tid >> 17;           // image index (B*C)
    const int half = j4 & 1;              // 0 -> col phases 0..3, 1 -> 4..7
    const int cb   = j4 >> 1;             // source column block

    const int cA = half ? cb : max(cb - 1, 0);
    const int cB = half ? min(cb + 1, WS - 1) : cb;
    const int rT = max(rb - 1, 0);
    const int rB = min(rb + 1, HS - 1);

    const float* __restrict__ base = img + (size_t)bc * (HS * WS);
    const float vTA = __ldg(base + rT * WS + cA);
    const float vTB = __ldg(base + rT * WS + cB);
    const float vMA = __ldg(base + rb * WS + cA);
    const float vMB = __ldg(base + rb * WS + cB);
    const float vBA = __ldg(base + rB * WS + cA);
    const float vBB = __ldg(base + rB * WS + cB);

    // Horizontal pass for each of the three source rows (4 column phases each).
    float hT[4], hM[4], hB[4];
    #pragma unroll
    for (int k = 0; k < 4; ++k) {
        const float wl = half ? W.wxl[k + 4] : W.wxl[k];
        const float wr = half ? W.wxr[k + 4] : W.wxr[k];
        hT[k] = wl * vTA + wr * vTB;
        hM[k] = wl * vMA + wr * vMB;
        hB[k] = wl * vBA + wr * vBB;
    }

    // Vertical pass: 8 output rows, each a coalesced float4 store.
    float4* __restrict__ orow =
        reinterpret_cast<float4*>(out) + ((size_t)bc * HO + (size_t)rb * 8) * 512 + j4;
    #pragma unroll
    for (int fy = 0; fy < 8; ++fy) {
        const float wl = W.wyl[fy];
        const float wr = W.wyr[fy];
        const float* hA = (fy < 4) ? hT : hM;   // resolved at compile time (unrolled)
        const float* hC = (fy < 4) ? hM : hB;
        float4 o;
        o.x = wl * hA[0] + wr * hC[0];
        o.y = wl * hA[1] + wr * hC[1];
        o.z = wl * hA[2] + wr * hC[2];
        o.w = wl * hA[3] + wr * hC[3];
        orow[(size_t)fy * 512] = o;
    }
}

extern "C" void kernel_launch(void* const* d_in, const int* in_sizes, int n_in,
                              void* d_out, int out_size) {
    (void)in_sizes; (void)n_in; (void)out_size;
    const float* img = (const float*)d_in[0];
    float* out = (float*)d_out;

    // Host-side weight computation (pure constants; deterministic every call).
    LzW W;
    const double pi = 3.14159265358979323846;
    for (int f = 0; f < 8; ++f) {
        const double delta = 1e-8 + f / 8.0;
        const int s = (f <= 3) ? (4 - f) : (12 - f);  // taps p < s hit the left source sample
        double wl = 0.0, wr = 0.0;
        for (int p = 0; p < 9; ++p) {
            const double x = delta + (double)(p - 4);
            const double a = x * pi;
            const double b = a * 0.25;  // lanczos a = 4
            const double w = (sin(a) / a) * (sin(b) / b);
            if (p < s) wl += w; else wr += w;
        }
        W.wxl[f] = (float)wl;  W.wxr[f] = (float)wr;
        W.wyl[f] = (float)wl;  W.wyr[f] = (float)wr;
    }

    // 8 images * 256 row-blocks * 512 float4-columns = 1,048,576 threads, 32 px each.
    const unsigned total_threads = (unsigned)NIMG * RBLK * 512;
    lz_main_kernel<<<total_threads / 256, 256>>>(img, out, W);
}

// round 15
// speedup vs baseline: 2.4623x; 1.0562x over previous
#include <cuda_runtime.h>
#include <math.h>

// LanczosUpsampling: (4,2,256,256) f32 -> (4,2,2048,2048), exact 8x separable lanczos(a=4).
//
// With scale exactly 8 there are only 8 fractional phases, and each phase's 9 taps
// span at most 2 source samples per axis. Separable form:
//   out[8rb+fy, 8cb+fx] = wy{l,r}[fy] (x) wx{l,r}[fx] applied to a 2x2 source patch,
// where fy<=3 uses rows (rb-1, rb), fy>=4 uses (rb, rb+1) (same for columns),
// and reflect padding reduces exactly to index clamping.
//
// One thread produces a 4-wide x 8-tall output patch (32 px): 6 scalar source loads,
// horizontal pass per source row, then 8 vertical combines + 8 coalesced STG.128.
// Stores use the streaming (.cs, evict-first) policy: the 128 MB output is never
// re-read, so keeping it out of L2 avoids thrashing the resident 2 MB source and
// smooths write-back. Weights (128 B) are host-computed, passed by value (const bank).

namespace {
constexpr int HS = 256;
constexpr int WS = 256;
constexpr int HO = 2048;
constexpr int NIMG = 8;      // B*C
constexpr int RBLK = HO / 8; // 256 source row blocks per image
}

struct LzW {
    float wxl[8], wxr[8];  // horizontal left/right aggregated tap sums per phase
    float wyl[8], wyr[8];  // vertical
};

__global__ __launch_bounds__(256)
void lz_main_kernel(const float* __restrict__ img, float* __restrict__ out, LzW W) {
    const unsigned tid = blockIdx.x * 256u + threadIdx.x;
    const int j4   = tid & 511;           // float4 slot within an output row
    const int rb   = (tid >> 9) & 255;    // source row block (8 output rows)
    const int bc   = tid >> 17;           // image index (B*C)
    const int half = j4 & 1;              // 0 -> col phases 0..3, 1 -> 4..7
    const int cb   = j4 >> 1;             // source column block

    const int cA = half ? cb : max(cb - 1, 0);
    const int cB = half ? min(cb + 1, WS - 1) : cb;
    const int rT = max(rb - 1, 0);
    const int rB = min(rb + 1, HS - 1);

    const float* __restrict__ base = img + (size_t)bc * (HS * WS);
    const float vTA = __ldg(base + rT * WS + cA);
    const float vTB = __ldg(base + rT * WS + cB);
    const float vMA = __ldg(base + rb * WS + cA);
    const float vMB = __ldg(base + rb * WS + cB);
    const float vBA = __ldg(base + rB * WS + cA);
    const float vBB = __ldg(base + rB * WS + cB);

    // Horizontal pass for each of the three source rows (4 column phases each).
    float hT[4], hM[4], hB[4];
    #pragma unroll
    for (int k = 0; k < 4; ++k) {
        const float wl = half ? W.wxl[k + 4] : W.wxl[k];
        const float wr = half ? W.wxr[k + 4] : W.wxr[k];
        hT[k] = wl * vTA + wr * vTB;
        hM[k] = wl * vMA + wr * vMB;
        hB[k] = wl * vBA + wr * vBB;
    }

    // Vertical pass: 8 output rows, each a coalesced streaming float4 store.
    float4* __restrict__ orow =
        reinterpret_cast<float4*>(out) + ((size_t)bc * HO + (size_t)rb * 8) * 512 + j4;
    #pragma unroll
    for (int fy = 0; fy < 8; ++fy) {
        const float wl = W.wyl[fy];
        const float wr = W.wyr[fy];
        const float* hA = (fy < 4) ? hT : hM;   // resolved at compile time (unrolled)
        const float* hC = (fy < 4) ? hM : hB;
        float4 o;
        o.x = wl * hA[0] + wr * hC[0];
        o.y = wl * hA[1] + wr * hC[1];
        o.z = wl * hA[2] + wr * hC[2];
        o.w = wl * hA[3] + wr * hC[3];
        __stcs(orow + (size_t)fy * 512, o);     // st.global.cs.v4.f32 (evict-first)
    }
}

extern "C" void kernel_launch(void* const* d_in, const int* in_sizes, int n_in,
                              void* d_out, int out_size) {
    (void)in_sizes; (void)n_in; (void)out_size;
    const float* img = (const float*)d_in[0];
    float* out = (float*)d_out;

    // Host-side weight computation (pure constants; deterministic every call).
    LzW W;
    const double pi = 3.14159265358979323846;
    for (int f = 0; f < 8; ++f) {
        const double delta = 1e-8 + f / 8.0;
        const int s = (f <= 3) ? (4 - f) : (12 - f);  // taps p < s hit the left source sample
        double wl = 0.0, wr = 0.0;
        for (int p = 0; p < 9; ++p) {
            const double x = delta + (double)(p - 4);
            const double a = x * pi;
            const double b = a * 0.25;  // lanczos a = 4
            const double w = (sin(a) / a) * (sin(b) / b);
            if (p < s) wl += w; else wr += w;
        }
        W.wxl[f] = (float)wl;  W.wxr[f] = (float)wr;
        W.wyl[f] = (float)wl;  W.wyr[f] = (float)wr;
    }

    // 8 images * 256 row-blocks * 512 float4-columns = 1,048,576 threads, 32 px each.
    const unsigned total_threads = (unsigned)NIMG * RBLK * 512;
    lz_main_kernel<<<total_threads / 256, 256>>>(img, out, W);
}